// round 2
// baseline (speedup 1.0000x reference)
#include <cuda_runtime.h>
#include <math.h>

// DictionaryMatchingTv — per-pixel nearest-dictionary-atom search with
// BIT-REPLICATED fp32 arithmetic (match XLA/Eigen rounding so argmin agrees
// exactly with the reference).
//
//   sig: [Npix, etl], db_mag: [D, etl], t2s: [D], b1s: [D], delta: [etl]
//   out: [t2 (Npix) | b1 (Npix) | min_dist (Npix)]
//
// Reference math (fp32):
//   sig1 = sig / ||sig||           (norm over all etl, seq mul/add reduction)
//   s    = (sig1*mask) / ||sig1*mask||
//   db   = (db_mag*mask) / ||db_mag*mask||
//   s2 = sum s^2, d2 = sum db^2    (seq mul/add, ~1 but not exactly 1)
//   dot  = fma-chain over e (GEMM k-loop order)
//   u    = (d2 + s2) - 2*dot ; dist = sqrt(max(u,0)); argmin (first min)

#define MAX_D   4096
#define MAX_ETL 16

__device__ int   g_cols[MAX_ETL];
__device__ int   g_ncols;
__device__ int   g_kpad;
__device__ float g_db[MAX_D * MAX_ETL];  // normalized dict, compact stride = kpad
__device__ float g_d2[MAX_D];

// ---------------------------------------------------------------------------
__global__ void prep_mask_kernel(const float* __restrict__ delta, int etl) {
    if (threadIdx.x == 0 && blockIdx.x == 0) {
        int cnt = 0;
        for (int e = 0; e < etl && e < MAX_ETL; e++) {
            if (__fmul_rn(delta[e], 1e-3f) < 1e-3f) g_cols[cnt++] = e;
        }
        g_ncols = cnt;
        g_kpad  = (cnt <= 8) ? 8 : 16;
    }
}

// ---------------------------------------------------------------------------
// Normalize each dictionary atom over masked cols, exact fp32 replication.
// ---------------------------------------------------------------------------
template <int K>
__global__ void prep_db_kernel(const float* __restrict__ db_mag, int D, int etl) {
    if (g_kpad != K) return;
    int d = blockIdx.x * blockDim.x + threadIdx.x;
    if (d >= D) return;
    const int ncols = g_ncols;

    float x[K];
#pragma unroll
    for (int k = 0; k < K; k++)
        x[k] = (k < ncols) ? db_mag[d * etl + g_cols[k]] : 0.f;

    // norm: sequential separate mul/add (XLA reduce; zeros add exactly 0)
    float ss = 0.f;
#pragma unroll
    for (int k = 0; k < K; k++) ss = __fadd_rn(ss, __fmul_rn(x[k], x[k]));
    float n = __fsqrt_rn(ss);
    float v[K];
#pragma unroll
    for (int k = 0; k < K; k++) v[k] = (n > 0.f) ? __fdiv_rn(x[k], n) : 0.f;

    // d2 = sum of squares of the ROUNDED normalized values
    float d2 = 0.f;
#pragma unroll
    for (int k = 0; k < K; k++) d2 = __fadd_rn(d2, __fmul_rn(v[k], v[k]));

#pragma unroll
    for (int k = 0; k < K; k++) g_db[d * K + k] = v[k];
    g_d2[d] = d2;
}

// ---------------------------------------------------------------------------
// Fused dot + argmin. One thread = one pixel.
// ---------------------------------------------------------------------------
template <int K>
__global__ void __launch_bounds__(256)
match_kernel(const float* __restrict__ sig,
             const float* __restrict__ t2s,
             const float* __restrict__ b1s,
             float* __restrict__ out,
             int Npix, int D, int etl) {
    if (g_kpad != K) return;

    constexpr int TS = 512;  // atoms per SMEM tile
    __shared__ float4 s_db[TS * K / 4];
    __shared__ float  s_d2[TS];
    __shared__ int    s_cols[MAX_ETL];
    __shared__ int    s_ncols;

    const int tid = threadIdx.x;
    if (tid < MAX_ETL) s_cols[tid] = g_cols[tid];
    if (tid == 0) s_ncols = g_ncols;
    __syncthreads();
    const int ncols = s_ncols;

    const int n = blockIdx.x * blockDim.x + tid;
    const bool active = (n < Npix);

    // ---- signal prep: two-stage normalization, exact fp32 replication ----
    float raw[MAX_ETL];
#pragma unroll
    for (int e = 0; e < MAX_ETL; e++)
        raw[e] = (active && e < etl) ? sig[n * etl + e] : 0.f;

    // stage 1: norm over ALL etl columns, sequential mul/add
    float ss1 = 0.f;
#pragma unroll
    for (int e = 0; e < MAX_ETL; e++) ss1 = __fadd_rn(ss1, __fmul_rn(raw[e], raw[e]));
    const float n1 = __fsqrt_rn(ss1);

    // gather masked columns of stage-1 result (mask multiply by 1.0 is exact)
    float t[K];
#pragma unroll
    for (int k = 0; k < K; k++) {
        float r = (k < ncols) ? raw[0] : 0.f;  // placeholder, real gather below
        (void)r;
        t[k] = 0.f;
    }
#pragma unroll
    for (int k = 0; k < K; k++) {
        if (k < ncols) {
            float x1 = (n1 > 0.f) ? __fdiv_rn(raw[s_cols[k]], n1) : 0.f;
            t[k] = x1;
        }
    }

    // stage 2: norm over masked columns
    float ss2 = 0.f;
#pragma unroll
    for (int k = 0; k < K; k++) ss2 = __fadd_rn(ss2, __fmul_rn(t[k], t[k]));
    const float n2 = __fsqrt_rn(ss2);
    float v[K];
#pragma unroll
    for (int k = 0; k < K; k++) v[k] = (n2 > 0.f) ? __fdiv_rn(t[k], n2) : 0.f;

    // s2 = sum of squares of rounded values
    float s2 = 0.f;
#pragma unroll
    for (int k = 0; k < K; k++) s2 = __fadd_rn(s2, __fmul_rn(v[k], v[k]));

    float bestDist = INFINITY;
    int   bestIdx  = 0;

    for (int tile0 = 0; tile0 < D; tile0 += TS) {
        const int cnt = min(TS, D - tile0);
        __syncthreads();
        {
            const float4* src = (const float4*)&g_db[tile0 * K];
            for (int idx = tid; idx < cnt * K / 4; idx += blockDim.x)
                s_db[idx] = src[idx];
            for (int idx = tid; idx < cnt; idx += blockDim.x)
                s_d2[idx] = g_d2[tile0 + idx];
        }
        __syncthreads();

        // strictly ascending atom order; strict < keeps FIRST minimum
        for (int a = 0; a < cnt; a++) {
            const float4* p = &s_db[a * (K / 4)];
            float dot = 0.f;
#pragma unroll
            for (int q = 0; q < K / 4; q++) {
                float4 w = p[q];
                dot = __fmaf_rn(w.x, v[4 * q + 0], dot);
                dot = __fmaf_rn(w.y, v[4 * q + 1], dot);
                dot = __fmaf_rn(w.z, v[4 * q + 2], dot);
                dot = __fmaf_rn(w.w, v[4 * q + 3], dot);
            }
            const float u  = __fadd_rn(__fadd_rn(s_d2[a], s2), -__fmul_rn(2.f, dot));
            const float uc = fmaxf(u, 0.f);
            if (uc < bestDist) { bestDist = uc; bestIdx = tile0 + a; }
        }
    }

    if (active) {
        out[n]            = t2s[bestIdx];
        out[Npix + n]     = b1s[bestIdx];
        out[2 * Npix + n] = __fsqrt_rn(bestDist);
    }
}

// ---------------------------------------------------------------------------
extern "C" void kernel_launch(void* const* d_in, const int* in_sizes, int n_in,
                              void* d_out, int out_size) {
    const float* sig    = (const float*)d_in[0];
    const float* db_mag = (const float*)d_in[1];
    const float* t2s    = (const float*)d_in[2];
    const float* b1s    = (const float*)d_in[3];
    const float* delta  = (const float*)d_in[4];

    const int etl  = in_sizes[4];
    const int D    = in_sizes[1] / etl;
    const int Npix = in_sizes[0] / etl;
    float* out = (float*)d_out;

    prep_mask_kernel<<<1, 32>>>(delta, etl);
    prep_db_kernel<8><<<(D + 127) / 128, 128>>>(db_mag, D, etl);
    prep_db_kernel<16><<<(D + 127) / 128, 128>>>(db_mag, D, etl);

    const int grid = (Npix + 255) / 256;
    match_kernel<8><<<grid, 256>>>(sig, t2s, b1s, out, Npix, D, etl);
    match_kernel<16><<<grid, 256>>>(sig, t2s, b1s, out, Npix, D, etl);
}

// round 3
// speedup vs baseline: 1.7363x; 1.7363x over previous
#include <cuda_runtime.h>
#include <math.h>

// DictionaryMatchingTv — per-pixel nearest-dictionary-atom search with
// bit-replicated fp32 arithmetic (argmin must agree exactly with reference).
//
// R3: occupancy x4 (block = 256 pixels x 4 dictionary chunks) + packed
// fma.rn.f32x2 atom-pair dot products. Whole interleaved dictionary staged
// in SMEM once per block; no syncs in hot loop.

#define MAX_D   4096
#define MAX_ETL 16

__device__ int   g_cols[MAX_ETL];
__device__ int   g_ncols;
__device__ int   g_kpad;
__device__ float g_db[MAX_D * MAX_ETL];        // flat (K=16 fallback path)
__device__ float g_dbp[(MAX_D / 2) * 16];      // K=8: pair-interleaved (a0k,a1k)
__device__ float g_d2[MAX_D];

typedef unsigned long long ull;

// ---------------- packed f32x2 helpers (per-element IEEE rn, == scalar) ----
__device__ __forceinline__ ull pack2(float lo, float hi) {
    ull r; asm("mov.b64 %0, {%1, %2};" : "=l"(r) : "f"(lo), "f"(hi)); return r;
}
__device__ __forceinline__ void unpack2(ull v, float& lo, float& hi) {
    asm("mov.b64 {%0, %1}, %2;" : "=f"(lo), "=f"(hi) : "l"(v));
}
__device__ __forceinline__ ull ffma2(ull a, ull b, ull c) {
    ull d; asm("fma.rn.f32x2 %0, %1, %2, %3;" : "=l"(d) : "l"(a), "l"(b), "l"(c)); return d;
}
__device__ __forceinline__ ull fadd2(ull a, ull b) {
    ull d; asm("add.rn.f32x2 %0, %1, %2;" : "=l"(d) : "l"(a), "l"(b)); return d;
}

// ---------------------------------------------------------------------------
__global__ void prep_mask_kernel(const float* __restrict__ delta, int etl) {
    if (threadIdx.x == 0 && blockIdx.x == 0) {
        int cnt = 0;
        for (int e = 0; e < etl && e < MAX_ETL; e++) {
            if (__fmul_rn(delta[e], 1e-3f) < 1e-3f) g_cols[cnt++] = e;
        }
        g_ncols = cnt;
        g_kpad  = (cnt <= 8) ? 8 : 16;
    }
}

// ---------------------------------------------------------------------------
// Normalize each dictionary atom over masked cols; exact fp32 replication.
// Writes pair-interleaved layout for the K=8 fast path, flat for K=16.
// ---------------------------------------------------------------------------
__global__ void prep_db_kernel(const float* __restrict__ db_mag, int D, int etl) {
    int d = blockIdx.x * blockDim.x + threadIdx.x;
    if (d >= D) return;
    const int ncols = g_ncols;

    float x[MAX_ETL];
#pragma unroll
    for (int k = 0; k < MAX_ETL; k++)
        x[k] = (k < ncols) ? db_mag[d * etl + g_cols[k]] : 0.f;

    float ss = 0.f;
#pragma unroll
    for (int k = 0; k < MAX_ETL; k++) ss = __fadd_rn(ss, __fmul_rn(x[k], x[k]));
    const float nn = __fsqrt_rn(ss);
    float v[MAX_ETL];
#pragma unroll
    for (int k = 0; k < MAX_ETL; k++) v[k] = (nn > 0.f) ? __fdiv_rn(x[k], nn) : 0.f;

    float d2 = 0.f;
#pragma unroll
    for (int k = 0; k < MAX_ETL; k++) d2 = __fadd_rn(d2, __fmul_rn(v[k], v[k]));
    g_d2[d] = d2;

    if (g_kpad == 8) {
#pragma unroll
        for (int k = 0; k < 8; k++)
            g_dbp[(d >> 1) * 16 + 2 * k + (d & 1)] = v[k];
    } else {
#pragma unroll
        for (int k = 0; k < MAX_ETL; k++) g_db[d * MAX_ETL + k] = v[k];
    }
}

// ---------------------------------------------------------------------------
// Shared signal prep (two-stage normalization, exact fp32 replication).
// ---------------------------------------------------------------------------
template <int K>
__device__ __forceinline__ void prep_signal(const float* __restrict__ sig,
                                            int n, bool active, int etl,
                                            const int* s_cols, int ncols,
                                            float* v, float& s2) {
    float raw[MAX_ETL];
#pragma unroll
    for (int e = 0; e < MAX_ETL; e++)
        raw[e] = (active && e < etl) ? sig[n * etl + e] : 0.f;

    float ss1 = 0.f;
#pragma unroll
    for (int e = 0; e < MAX_ETL; e++) ss1 = __fadd_rn(ss1, __fmul_rn(raw[e], raw[e]));
    const float n1 = __fsqrt_rn(ss1);

    float t[K];
#pragma unroll
    for (int k = 0; k < K; k++) {
        t[k] = 0.f;
        if (k < ncols) t[k] = (n1 > 0.f) ? __fdiv_rn(raw[s_cols[k]], n1) : 0.f;
    }
    float ss2 = 0.f;
#pragma unroll
    for (int k = 0; k < K; k++) ss2 = __fadd_rn(ss2, __fmul_rn(t[k], t[k]));
    const float n2 = __fsqrt_rn(ss2);
#pragma unroll
    for (int k = 0; k < K; k++) v[k] = (n2 > 0.f) ? __fdiv_rn(t[k], n2) : 0.f;

    s2 = 0.f;
#pragma unroll
    for (int k = 0; k < K; k++) s2 = __fadd_rn(s2, __fmul_rn(v[k], v[k]));
}

// ---------------------------------------------------------------------------
// K=8 fast path: 1024 threads = 256 pixels x 4 D-chunks. Whole dictionary in
// SMEM (pair-interleaved). fma.rn.f32x2 computes two atoms' dots at once.
// ---------------------------------------------------------------------------
#define NPB 256   // pixels per block
#define NG  4     // dictionary chunks (thread groups)

__global__ void __launch_bounds__(NPB * NG, 1)
match8_kernel(const float* __restrict__ sig,
              const float* __restrict__ t2s,
              const float* __restrict__ b1s,
              float* __restrict__ out,
              int Npix, int D, int etl) {
    if (g_kpad != 8) return;

    extern __shared__ char smem_raw[];
    const int P  = (D + 1) >> 1;        // atom pairs
    const int pf = P * 16;              // interleaved floats
    float* s_db = (float*)smem_raw;
    float* s_d2 = s_db + pf;
    const int d2pad = (D + 3) & ~3;
    float* s_bu = s_d2 + d2pad;
    int*   s_bi = (int*)(s_bu + NPB * NG);

    __shared__ int s_cols[MAX_ETL];
    __shared__ int s_ncols;

    const int tid   = threadIdx.x;
    const int group = tid >> 8;         // 0..3
    const int px    = tid & (NPB - 1);
    if (tid < MAX_ETL) s_cols[tid] = g_cols[tid];
    if (tid == 0) s_ncols = g_ncols;

    // Stage dictionary into SMEM (vectorized; pf is a multiple of 16).
    {
        const float4* src = (const float4*)g_dbp;
        float4* dst = (float4*)s_db;
        for (int i = tid; i < pf / 4; i += NPB * NG) dst[i] = src[i];
        for (int i = tid; i < D; i += NPB * NG) s_d2[i] = g_d2[i];
    }
    __syncthreads();
    const int ncols = s_ncols;

    const int n = blockIdx.x * NPB + px;
    const bool active = (n < Npix);

    float v[8]; float s2;
    prep_signal<8>(sig, n, active, etl, s_cols, ncols, v, s2);

    ull vk2[8];
#pragma unroll
    for (int k = 0; k < 8; k++) vk2[k] = pack2(v[k], v[k]);
    const ull s2p  = pack2(s2, s2);
    const ull neg2 = pack2(-2.f, -2.f);

    // This group's chunk [c0, c1)
    const int L  = (D + NG - 1) / NG;
    const int c0 = group * L;
    const int c1 = min(c0 + L, D);

    float bestU  = INFINITY;
    int   bestI  = 0;

    int a = c0;
    // scalar head if chunk starts mid-pair
    if ((a & 1) && a < c1) {
        const float* p = &s_db[(a >> 1) * 16];
        float dot = 0.f;
#pragma unroll
        for (int k = 0; k < 8; k++) dot = __fmaf_rn(p[2 * k + 1], v[k], dot);
        float u = fmaxf(__fmaf_rn(-2.f, dot, __fadd_rn(s_d2[a], s2)), 0.f);
        if (u < bestU) { bestU = u; bestI = a; }
        a++;
    }
#pragma unroll 2
    for (; a + 2 <= c1; a += 2) {
        const ull* pp = (const ull*)&s_db[(a >> 1) * 16];
        ull acc = pack2(0.f, 0.f);
        acc = ffma2(pp[0], vk2[0], acc);
        acc = ffma2(pp[1], vk2[1], acc);
        acc = ffma2(pp[2], vk2[2], acc);
        acc = ffma2(pp[3], vk2[3], acc);
        acc = ffma2(pp[4], vk2[4], acc);
        acc = ffma2(pp[5], vk2[5], acc);
        acc = ffma2(pp[6], vk2[6], acc);
        acc = ffma2(pp[7], vk2[7], acc);
        const ull d2pair = *(const ull*)&s_d2[a];
        const ull h2 = fadd2(d2pair, s2p);
        const ull u2 = ffma2(neg2, acc, h2);   // exact: 2*dot has no rounding
        float u0, u1; unpack2(u2, u0, u1);
        u0 = fmaxf(u0, 0.f);
        u1 = fmaxf(u1, 0.f);
        if (u0 < bestU) { bestU = u0; bestI = a; }
        if (u1 < bestU) { bestU = u1; bestI = a + 1; }
    }
    // scalar tail
    if (a < c1) {
        const float* p = &s_db[(a >> 1) * 16];
        float dot = 0.f;
#pragma unroll
        for (int k = 0; k < 8; k++) dot = __fmaf_rn(p[2 * k], v[k], dot);
        float u = fmaxf(__fmaf_rn(-2.f, dot, __fadd_rn(s_d2[a], s2)), 0.f);
        if (u < bestU) { bestU = u; bestI = a; }
    }

    // merge across groups (ascending group = ascending atom index; strict <)
    s_bu[group * NPB + px] = bestU;
    s_bi[group * NPB + px] = bestI;
    __syncthreads();
    if (group == 0 && active) {
        float b = s_bu[px]; int bi = s_bi[px];
#pragma unroll
        for (int g = 1; g < NG; g++) {
            float ug = s_bu[g * NPB + px];
            if (ug < b) { b = ug; bi = s_bi[g * NPB + px]; }
        }
        out[n]            = t2s[bi];
        out[Npix + n]     = b1s[bi];
        out[2 * Npix + n] = __fsqrt_rn(b);
    }
}

// ---------------------------------------------------------------------------
// K=16 fallback (generic, tiled; unused for this dataset but keeps coverage).
// ---------------------------------------------------------------------------
__global__ void __launch_bounds__(256)
match16_kernel(const float* __restrict__ sig,
               const float* __restrict__ t2s,
               const float* __restrict__ b1s,
               float* __restrict__ out,
               int Npix, int D, int etl) {
    if (g_kpad != 16) return;
    constexpr int K = 16, TS = 512;
    __shared__ float4 s_db[TS * K / 4];
    __shared__ float  s_d2[TS];
    __shared__ int    s_cols[MAX_ETL];
    __shared__ int    s_ncols;

    const int tid = threadIdx.x;
    if (tid < MAX_ETL) s_cols[tid] = g_cols[tid];
    if (tid == 0) s_ncols = g_ncols;
    __syncthreads();
    const int ncols = s_ncols;
    const int n = blockIdx.x * blockDim.x + tid;
    const bool active = (n < Npix);

    float v[K]; float s2;
    prep_signal<K>(sig, n, active, etl, s_cols, ncols, v, s2);

    float bestU = INFINITY; int bestI = 0;
    for (int tile0 = 0; tile0 < D; tile0 += TS) {
        const int cnt = min(TS, D - tile0);
        __syncthreads();
        const float4* src = (const float4*)&g_db[tile0 * K];
        for (int idx = tid; idx < cnt * K / 4; idx += blockDim.x) s_db[idx] = src[idx];
        for (int idx = tid; idx < cnt; idx += blockDim.x) s_d2[idx] = g_d2[tile0 + idx];
        __syncthreads();
        for (int aa = 0; aa < cnt; aa++) {
            const float4* p = &s_db[aa * (K / 4)];
            float dot = 0.f;
#pragma unroll
            for (int q = 0; q < K / 4; q++) {
                float4 w = p[q];
                dot = __fmaf_rn(w.x, v[4 * q + 0], dot);
                dot = __fmaf_rn(w.y, v[4 * q + 1], dot);
                dot = __fmaf_rn(w.z, v[4 * q + 2], dot);
                dot = __fmaf_rn(w.w, v[4 * q + 3], dot);
            }
            const float u = fmaxf(__fmaf_rn(-2.f, dot, __fadd_rn(s_d2[aa], s2)), 0.f);
            if (u < bestU) { bestU = u; bestI = tile0 + aa; }
        }
    }
    if (active) {
        out[n]            = t2s[bestI];
        out[Npix + n]     = b1s[bestI];
        out[2 * Npix + n] = __fsqrt_rn(bestU);
    }
}

// ---------------------------------------------------------------------------
extern "C" void kernel_launch(void* const* d_in, const int* in_sizes, int n_in,
                              void* d_out, int out_size) {
    const float* sig    = (const float*)d_in[0];
    const float* db_mag = (const float*)d_in[1];
    const float* t2s    = (const float*)d_in[2];
    const float* b1s    = (const float*)d_in[3];
    const float* delta  = (const float*)d_in[4];

    const int etl  = in_sizes[4];
    const int D    = in_sizes[1] / etl;
    const int Npix = in_sizes[0] / etl;
    float* out = (float*)d_out;

    prep_mask_kernel<<<1, 32>>>(delta, etl);
    prep_db_kernel<<<(D + 127) / 128, 128>>>(db_mag, D, etl);

    // dynamic SMEM for the fast path
    const int P  = (D + 1) >> 1;
    const int d2pad = (D + 3) & ~3;
    size_t smem = (size_t)(P * 16 + d2pad + NPB * NG) * 4 + (size_t)(NPB * NG) * 4;
    cudaFuncSetAttribute(match8_kernel,
                         cudaFuncAttributeMaxDynamicSharedMemorySize, (int)smem);

    const int grid8 = (Npix + NPB - 1) / NPB;
    match8_kernel<<<grid8, NPB * NG, smem>>>(sig, t2s, b1s, out, Npix, D, etl);
    match16_kernel<<<(Npix + 255) / 256, 256>>>(sig, t2s, b1s, out, Npix, D, etl);
}